// round 16
// baseline (speedup 1.0000x reference)
#include <cuda_runtime.h>
#include <cuda_bf16.h>
#include <cstdint>

#define kE 16
#define kT 1024
#define kH 2880
#define kI 2880

#define BM 128
#define BN 64
#define BK 64
#define NTH 256

#define A_ST_BYTES 16384
#define B_ST_BYTES 8192
#define STAGE_BYTES (A_ST_BYTES + B_ST_BYTES)

__device__ __align__(16) __nv_bfloat16 g_hbuf[(size_t)kE * kT * kI];   // h, bf16

__device__ __forceinline__ uint32_t smem_u32(const void* p) {
    uint32_t a;
    asm("{ .reg .u64 t; cvta.to.shared.u64 t, %1; cvt.u32.u64 %0, t; }" : "=r"(a) : "l"(p));
    return a;
}
__device__ __forceinline__ uint32_t swz(uint32_t off) { return off ^ ((off >> 3) & 0x70); }
__device__ __forceinline__ uint32_t packbf(float lo, float hi) {
    __nv_bfloat162 b = __floats2bfloat162_rn(lo, hi);
    return *reinterpret_cast<uint32_t*>(&b);
}
__device__ __forceinline__ float bfr(float x) {   // f32 -> bf16 -> f32 rounding
    return __bfloat162float(__float2bfloat16(x));
}
__device__ __forceinline__ void ldsm4(uint32_t r[4], uint32_t addr) {
    asm volatile("ldmatrix.sync.aligned.m8n8.x4.shared.b16 {%0,%1,%2,%3}, [%4];"
                 : "=r"(r[0]), "=r"(r[1]), "=r"(r[2]), "=r"(r[3]) : "r"(addr) : "memory");
}
__device__ __forceinline__ void ldsm4t(uint32_t r[4], uint32_t addr) {
    asm volatile("ldmatrix.sync.aligned.m8n8.x4.trans.shared.b16 {%0,%1,%2,%3}, [%4];"
                 : "=r"(r[0]), "=r"(r[1]), "=r"(r[2]), "=r"(r[3]) : "r"(addr) : "memory");
}
__device__ __forceinline__ void mma16816(float c[4], const uint32_t a[4],
                                         uint32_t b0, uint32_t b1) {
    asm volatile(
        "mma.sync.aligned.m16n8k16.row.col.f32.bf16.bf16.f32 "
        "{%0,%1,%2,%3}, {%4,%5,%6,%7}, {%8,%9}, {%0,%1,%2,%3};"
        : "+f"(c[0]), "+f"(c[1]), "+f"(c[2]), "+f"(c[3])
        : "r"(a[0]), "r"(a[1]), "r"(a[2]), "r"(a[3]), "r"(b0), "r"(b1));
}

// MODE 0 (GEMM1): A = x (f32, bf16-valued), W = wgu, K = kH.
//   Eager bf16 chain, decomposed sigmoid, alpha = bf16(1.702) = 1.703125.
// MODE 1 (GEMM2): A = g_hbuf (bf16), W = wd, K = kI.
//   out = bf16(bf16(acc) + bias), stored f32.
template <int MODE>
__global__ __launch_bounds__(NTH, 2)
void mma_gemm(const float* __restrict__ Af,
              const float* __restrict__ W_all,
              const float* __restrict__ bias_all,
              float* __restrict__ OUT,
              int K, int Nw) {
    __shared__ __align__(128) char smem[2 * STAGE_BYTES];   // 48 KB
    const uint32_t sbase = smem_u32(smem);

    const int tid = threadIdx.x, wid = tid >> 5, lane = tid & 31;
    const int e = blockIdx.z, m0 = blockIdx.x * BM, n0 = blockIdx.y * BN;
    const int warp_m = wid >> 1;
    const int warp_n = wid & 1;

    const float* W = W_all + (size_t)e * (size_t)K * Nw + n0;
    const float* bias = bias_all + (size_t)e * Nw + n0;
    const float* A32 = (MODE == 0) ? Af + ((size_t)e * kT + m0) * (size_t)K : nullptr;
    const __nv_bfloat16* A16 = (MODE == 1)
        ? g_hbuf + ((size_t)e * kT + m0) * (size_t)K : nullptr;

    float acc[2][4][4];
    #pragma unroll
    for (int i = 0; i < 2; ++i)
        #pragma unroll
        for (int j = 0; j < 4; ++j)
            #pragma unroll
            for (int q = 0; q < 4; ++q) acc[i][j][q] = 0.0f;

    const int am = tid >> 3, akc = tid & 7;
    const int bk = tid >> 3, bnc = tid & 7;

    uint4 aR[4], bR[2];

    auto load_regs = [&](int it) {
        const int k0 = it * BK;
        #pragma unroll
        for (int i = 0; i < 4; ++i) {
            const int m = am + 32 * i;
            if (MODE == 0) {
                const float4* p = reinterpret_cast<const float4*>(
                    A32 + (size_t)m * K + k0 + akc * 8);
                const float4 f0 = p[0], f1 = p[1];
                aR[i].x = packbf(f0.x, f0.y); aR[i].y = packbf(f0.z, f0.w);
                aR[i].z = packbf(f1.x, f1.y); aR[i].w = packbf(f1.z, f1.w);
            } else {
                aR[i] = *reinterpret_cast<const uint4*>(
                    A16 + (size_t)m * K + k0 + akc * 8);
            }
        }
        #pragma unroll
        for (int i = 0; i < 2; ++i) {
            const int krow = k0 + bk + 32 * i;
            const float4* p = reinterpret_cast<const float4*>(
                W + (size_t)krow * Nw + bnc * 8);
            const float4 f0 = p[0], f1 = p[1];
            bR[i].x = packbf(f0.x, f0.y); bR[i].y = packbf(f0.z, f0.w);
            bR[i].z = packbf(f1.x, f1.y); bR[i].w = packbf(f1.z, f1.w);
        }
    };

    const int kiters = K / BK;    // 45
    int stage = 0;
    load_regs(0);

    for (int it = 0; it < kiters; ++it) {
        {
            char* stA = smem + stage * STAGE_BYTES;
            char* stB = stA + A_ST_BYTES;
            #pragma unroll
            for (int i = 0; i < 4; ++i) {
                const int m = am + 32 * i;
                *reinterpret_cast<uint4*>(stA + swz((uint32_t)(m * 128 + akc * 16))) = aR[i];
            }
            #pragma unroll
            for (int i = 0; i < 2; ++i) {
                const int kk = bk + 32 * i;
                *reinterpret_cast<uint4*>(stB + swz((uint32_t)(kk * 128 + bnc * 16))) = bR[i];
            }
        }
        __syncthreads();

        if (it + 1 < kiters) load_regs(it + 1);

        const uint32_t stA = sbase + stage * STAGE_BYTES;
        const uint32_t stB = stA + A_ST_BYTES;
        #pragma unroll
        for (int ks = 0; ks < 4; ++ks) {
            uint32_t a[2][4], b[2][4];
            #pragma unroll
            for (int mi = 0; mi < 2; ++mi) {
                const uint32_t off = (uint32_t)((warp_m * 32 + mi * 16 + (lane & 15)) * 128
                                                + ks * 32 + (lane >> 4) * 16);
                ldsm4(a[mi], stA + swz(off));
            }
            #pragma unroll
            for (int nt = 0; nt < 2; ++nt) {
                const uint32_t off = (uint32_t)((ks * 16 + (lane & 15)) * 128
                                                + (warp_n * 32 + nt * 16 + (lane >> 4) * 8) * 2);
                ldsm4t(b[nt], stB + swz(off));
            }
            #pragma unroll
            for (int mi = 0; mi < 2; ++mi)
                #pragma unroll
                for (int nt = 0; nt < 2; ++nt) {
                    mma16816(acc[mi][2 * nt],     a[mi], b[nt][0], b[nt][1]);
                    mma16816(acc[mi][2 * nt + 1], a[mi], b[nt][2], b[nt][3]);
                }
        }
        __syncthreads();
        stage ^= 1;
    }

    // ------- epilogue: eager bf16 chain, decomposed sigmoid, alpha=1.703125 ---
    const int rr = lane >> 2;
    const int cp = (lane & 3) * 2;

    #pragma unroll
    for (int mi = 0; mi < 2; ++mi) {
        #pragma unroll
        for (int h8 = 0; h8 < 2; ++h8) {
            const int row = m0 + warp_m * 32 + mi * 16 + h8 * 8 + rr;
            #pragma unroll
            for (int ni = 0; ni < 4; ++ni) {
                const int n = warp_n * 32 + ni * 8 + cp;
                const float c0 = bfr(acc[mi][ni][h8 * 2 + 0]);   // einsum -> bf16
                const float c1 = bfr(acc[mi][ni][h8 * 2 + 1]);
                const float2 bb = *reinterpret_cast<const float2*>(bias + n);
                if (MODE == 0) {
                    const float g    = bfr(c0 + bb.x);           // + bias (bf16)
                    const float u    = bfr(c1 + bb.y);
                    const float gate = fminf(g, 7.0f);           // exact
                    const float up   = fminf(fmaxf(u, -7.0f), 7.0f);
                    const float t    = bfr(gate * 1.703125f);    // alpha = bf16(1.702)
                    const float ex   = bfr(expf(-t));            // decomposed expit
                    const float den  = bfr(1.0f + ex);
                    const float s    = bfr(1.0f / den);
                    const float glu  = bfr(gate * s);
                    const float up1  = bfr(up + 1.0f);
                    g_hbuf[((size_t)e * kT + row) * (size_t)kI + ((n0 + n) >> 1)] =
                        __float2bfloat16(up1 * glu);             // h -> bf16
                } else {
                    const float o0 = bfr(c0 + bb.x);             // out -> bf16, f32 store
                    const float o1 = bfr(c1 + bb.y);
                    *reinterpret_cast<float2*>(
                        OUT + ((size_t)e * kT + row) * (size_t)kH + n0 + n) =
                        make_float2(o0, o1);
                }
            }
        }
    }
}

extern "C" void kernel_launch(void* const* d_in, const int* in_sizes, int n_in,
                              void* d_out, int out_size) {
    const float* x   = (const float*)d_in[0];
    const float* wgu = (const float*)d_in[1];
    const float* bgu = (const float*)d_in[2];
    const float* wd  = (const float*)d_in[3];
    const float* bd  = (const float*)d_in[4];
    float* out = (float*)d_out;

    dim3 g1(kT / BM, (2 * kI) / BN, kE);    // (8, 90, 16)
    mma_gemm<0><<<g1, NTH>>>(x, wgu, bgu, nullptr, kH, 2 * kI);

    dim3 g2(kT / BM, kH / BN, kE);          // (8, 45, 16)
    mma_gemm<1><<<g2, NTH>>>(nullptr, wd, bd, out, kI, kH);
}

// round 17
// speedup vs baseline: 1.5918x; 1.5918x over previous
#include <cuda_runtime.h>
#include <cuda_bf16.h>
#include <cstdint>

#define kE 16
#define kT 1024
#define kH 2880
#define kI 2880

#define BM 256
#define BN 64
#define BK 32
#define NTH 256
#define NSTG 3

#define A_ST 16384                 /* 256 rows x 64B (32 bf16)  */
#define B_ST 4096                  /* 32 k-rows x 128B (64 bf16) */
#define STAGE (A_ST + B_ST)        /* 20480 */
#define SMEM_TOTAL (NSTG * STAGE)  /* 61440 */

__device__ __align__(16) __nv_bfloat16 g_hbuf[(size_t)kE * kT * kI];   // h (bf16)
__device__ __align__(16) __nv_bfloat16 g_xbuf[(size_t)kE * kT * kH];   // x (bf16)

__device__ __forceinline__ uint32_t smem_u32(const void* p) {
    uint32_t a;
    asm("{ .reg .u64 t; cvta.to.shared.u64 t, %1; cvt.u32.u64 %0, t; }" : "=r"(a) : "l"(p));
    return a;
}
__device__ __forceinline__ uint32_t swz128(uint32_t off) { return off ^ ((off >> 3) & 0x70); }
__device__ __forceinline__ uint32_t swz64(uint32_t off)  { return off ^ (((off >> 7) & 3) << 4); }
__device__ __forceinline__ uint32_t packbf(float lo, float hi) {
    __nv_bfloat162 b = __floats2bfloat162_rn(lo, hi);
    return *reinterpret_cast<uint32_t*>(&b);
}
__device__ __forceinline__ float bfr(float x) {
    return __bfloat162float(__float2bfloat16(x));
}
__device__ __forceinline__ void cpa16(uint32_t dst, const void* src) {
    asm volatile("cp.async.cg.shared.global [%0], [%1], 16;" :: "r"(dst), "l"(src));
}
#define CP_COMMIT() asm volatile("cp.async.commit_group;" ::: "memory")
#define CP_WAIT1()  asm volatile("cp.async.wait_group 1;" ::: "memory")

__device__ __forceinline__ void ldsm4(uint32_t r[4], uint32_t addr) {
    asm volatile("ldmatrix.sync.aligned.m8n8.x4.shared.b16 {%0,%1,%2,%3}, [%4];"
                 : "=r"(r[0]), "=r"(r[1]), "=r"(r[2]), "=r"(r[3]) : "r"(addr) : "memory");
}
__device__ __forceinline__ void ldsm4t(uint32_t r[4], uint32_t addr) {
    asm volatile("ldmatrix.sync.aligned.m8n8.x4.trans.shared.b16 {%0,%1,%2,%3}, [%4];"
                 : "=r"(r[0]), "=r"(r[1]), "=r"(r[2]), "=r"(r[3]) : "r"(addr) : "memory");
}
__device__ __forceinline__ void mma16816(float c[4], const uint32_t a[4],
                                         uint32_t b0, uint32_t b1) {
    asm volatile(
        "mma.sync.aligned.m16n8k16.row.col.f32.bf16.bf16.f32 "
        "{%0,%1,%2,%3}, {%4,%5,%6,%7}, {%8,%9}, {%0,%1,%2,%3};"
        : "+f"(c[0]), "+f"(c[1]), "+f"(c[2]), "+f"(c[3])
        : "r"(a[0]), "r"(a[1]), "r"(a[2]), "r"(a[3]), "r"(b0), "r"(b1));
}

// one-shot f32 -> bf16 conversion (x)
__global__ void cvt_kernel(const float* __restrict__ in, long long nchunks) {
    const long long i = (long long)blockIdx.x * NTH + threadIdx.x;
    if (i < nchunks) {
        const float4 a = reinterpret_cast<const float4*>(in)[2 * i];
        const float4 b = reinterpret_cast<const float4*>(in)[2 * i + 1];
        uint4 o;
        o.x = packbf(a.x, a.y); o.y = packbf(a.z, a.w);
        o.z = packbf(b.x, b.y); o.w = packbf(b.z, b.w);
        reinterpret_cast<uint4*>(g_xbuf)[i] = o;
    }
}

// MODE 0 (GEMM1): A = g_xbuf, W = wgu (f32), Nw = 5760 -> gated h into g_hbuf
// MODE 1 (GEMM2): A = g_hbuf, W = wd  (f32), Nw = 2880 -> out f32 (bf16-rounded)
template <int MODE>
__global__ __launch_bounds__(NTH, 2)
void mma_gemm(const float* __restrict__ W_all,
              const float* __restrict__ bias_all,
              float* __restrict__ OUT,
              int Nw) {
    extern __shared__ __align__(128) char smem[];
    const uint32_t sbase = smem_u32(smem);

    const int tid = threadIdx.x, wid = tid >> 5, lane = tid & 31;
    const int e = blockIdx.z, m0 = blockIdx.x * BM, n0 = blockIdx.y * BN;
    const int warp_m = wid >> 1;     // 0..3 -> 64 rows each
    const int warp_n = wid & 1;      // 0..1 -> 32 cols each

    const __nv_bfloat16* Ab = ((MODE == 0) ? g_xbuf : g_hbuf)
                              + ((size_t)e * kT + m0) * (size_t)kH;
    const float* W = W_all + (size_t)e * (size_t)kH * Nw + n0;
    const float* bias = bias_all + (size_t)e * Nw + n0;

    float acc[4][4][4];
    #pragma unroll
    for (int i = 0; i < 4; ++i)
        #pragma unroll
        for (int j = 0; j < 4; ++j)
            #pragma unroll
            for (int q = 0; q < 4; ++q) acc[i][j][q] = 0.0f;

    // A cp.async mapping: 1024 chunks of 16B (row m, unit u of 4)
    const int am = tid >> 2, au = tid & 3;
    // B f32 loader mapping: 512 units of 16B (k-row, 16B n-chunk)
    const int bk0 = tid >> 4, bc = tid & 15;

    float4 bRf[2];

    auto cpA = [&](int it) {
        const int k0 = it * BK;
        const uint32_t st = sbase + (uint32_t)(it % NSTG) * STAGE;
        #pragma unroll
        for (int i = 0; i < 4; ++i) {
            const int m = am + 64 * i;
            cpa16(st + swz64((uint32_t)(m * 64 + au * 16)),
                  Ab + (size_t)m * kH + k0 + au * 8);
        }
    };
    auto ldB = [&](int it) {
        const int k0 = it * BK;
        #pragma unroll
        for (int i = 0; i < 2; ++i) {
            const int kk = bk0 + 16 * i;
            bRf[i] = *reinterpret_cast<const float4*>(
                W + (size_t)(k0 + kk) * Nw + bc * 4);
        }
    };
    auto stsB = [&](int it) {
        char* stB = smem + (it % NSTG) * STAGE + A_ST;
        #pragma unroll
        for (int i = 0; i < 2; ++i) {
            const int kk = bk0 + 16 * i;
            uint2 v;
            v.x = packbf(bRf[i].x, bRf[i].y);
            v.y = packbf(bRf[i].z, bRf[i].w);
            *reinterpret_cast<uint2*>(stB + swz128((uint32_t)(kk * 128 + bc * 8))) = v;
        }
    };

    const int kiters = kH / BK;   // 90
    cpA(0); CP_COMMIT();
    cpA(1); CP_COMMIT();
    ldB(0);

    for (int it = 0; it < kiters; ++it) {
        stsB(it);
        CP_WAIT1();
        __syncthreads();
        if (it + 2 < kiters) cpA(it + 2);
        CP_COMMIT();
        if (it + 1 < kiters) ldB(it + 1);

        const uint32_t stA = sbase + (uint32_t)(it % NSTG) * STAGE;
        const uint32_t stB = stA + A_ST;
        #pragma unroll
        for (int ks = 0; ks < 2; ++ks) {
            uint32_t a[4][4], b[2][4];
            #pragma unroll
            for (int mi = 0; mi < 4; ++mi) {
                const uint32_t off = (uint32_t)((warp_m * 64 + mi * 16 + (lane & 15)) * 64
                                                + ks * 32 + (lane >> 4) * 16);
                ldsm4(a[mi], stA + swz64(off));
            }
            #pragma unroll
            for (int nt = 0; nt < 2; ++nt) {
                const uint32_t off = (uint32_t)((ks * 16 + (lane & 15)) * 128
                                                + (warp_n * 32 + nt * 16 + (lane >> 4) * 8) * 2);
                ldsm4t(b[nt], stB + swz128(off));
            }
            #pragma unroll
            for (int mi = 0; mi < 4; ++mi)
                #pragma unroll
                for (int nt = 0; nt < 2; ++nt) {
                    mma16816(acc[mi][2 * nt],     a[mi], b[nt][0], b[nt][1]);
                    mma16816(acc[mi][2 * nt + 1], a[mi], b[nt][2], b[nt][3]);
                }
        }
        __syncthreads();
    }

    // ------- epilogue: identical numerics to the passing R16 kernel -------
    const int rr = lane >> 2;
    const int cp = (lane & 3) * 2;

    #pragma unroll
    for (int mi = 0; mi < 4; ++mi) {
        #pragma unroll
        for (int h8 = 0; h8 < 2; ++h8) {
            const int row = m0 + warp_m * 64 + mi * 16 + h8 * 8 + rr;
            #pragma unroll
            for (int nj = 0; nj < 4; ++nj) {
                const int n = warp_n * 32 + nj * 8 + cp;
                const float c0 = bfr(acc[mi][nj][h8 * 2 + 0]);   // einsum -> bf16
                const float c1 = bfr(acc[mi][nj][h8 * 2 + 1]);
                const float2 bb = *reinterpret_cast<const float2*>(bias + n);
                if (MODE == 0) {
                    const float g    = bfr(c0 + bb.x);
                    const float u    = bfr(c1 + bb.y);
                    const float gate = fminf(g, 7.0f);
                    const float up   = fminf(fmaxf(u, -7.0f), 7.0f);
                    const float t    = bfr(gate * 1.703125f);    // alpha = bf16(1.702)
                    const float ex   = bfr(expf(-t));            // decomposed expit
                    const float den  = bfr(1.0f + ex);
                    const float s    = bfr(1.0f / den);
                    const float glu  = bfr(gate * s);
                    const float up1  = bfr(up + 1.0f);
                    g_hbuf[((size_t)e * kT + row) * (size_t)kI + ((n0 + n) >> 1)] =
                        __float2bfloat16(up1 * glu);
                } else {
                    const float o0 = bfr(c0 + bb.x);
                    const float o1 = bfr(c1 + bb.y);
                    *reinterpret_cast<float2*>(
                        OUT + ((size_t)e * kT + row) * (size_t)kH + n0 + n) =
                        make_float2(o0, o1);
                }
            }
        }
    }
}

extern "C" void kernel_launch(void* const* d_in, const int* in_sizes, int n_in,
                              void* d_out, int out_size) {
    const float* x   = (const float*)d_in[0];
    const float* wgu = (const float*)d_in[1];
    const float* bgu = (const float*)d_in[2];
    const float* wd  = (const float*)d_in[3];
    const float* bd  = (const float*)d_in[4];
    float* out = (float*)d_out;

    cudaFuncSetAttribute(mma_gemm<0>,
                         cudaFuncAttributeMaxDynamicSharedMemorySize, SMEM_TOTAL);
    cudaFuncSetAttribute(mma_gemm<1>,
                         cudaFuncAttributeMaxDynamicSharedMemorySize, SMEM_TOTAL);

    // x (f32) -> g_xbuf (bf16): 47,185,920 elems = 5,898,240 8-elem chunks
    const long long nchunks = (long long)kE * kT * kH / 8;
    cvt_kernel<<<(int)((nchunks + NTH - 1) / NTH), NTH>>>(x, nchunks);

    // GEMM1: g_xbuf @ wgu + bgu -> gated -> g_hbuf
    dim3 g1(kT / BM, (2 * kI) / BN, kE);    // (4, 90, 16)
    mma_gemm<0><<<g1, NTH, SMEM_TOTAL>>>(wgu, bgu, nullptr, 2 * kI);

    // GEMM2: g_hbuf @ wd + bd -> out
    dim3 g2(kT / BM, kH / BN, kE);          // (4, 45, 16)
    mma_gemm<1><<<g2, NTH, SMEM_TOTAL>>>(wd, bd, out, kH);
}